// round 1
// baseline (speedup 1.0000x reference)
#include <cuda_runtime.h>
#include <math.h>

#define DIM       128
#define NPARAMS   8384      // 128 mean + 8256 packed L
#define NTHREADS  256

// Dynamic smem layout:
//  Lt[128][128]  : L transposed, Lt[j][i] = L[i][j]   (16384 floats)
//  s_eps[128], s_ld[128] (log diag), s_diag[128] (Sigma diag), s_red[8]
#define SMEM_FLOATS (DIM*DIM + 3*DIM + 8)

__global__ __launch_bounds__(NTHREADS)
void fld_kernel(const float* __restrict__ params,
                const float* __restrict__ eps,
                float* __restrict__ sample,
                float* __restrict__ kl,
                float* __restrict__ sigma)
{
    extern __shared__ float sm[];
    float (*Lt)[DIM] = (float (*)[DIM])sm;
    float* s_eps  = sm + DIM*DIM;
    float* s_ld   = s_eps  + DIM;
    float* s_diag = s_ld   + DIM;
    float* s_red  = s_diag + DIM;

    const int b   = blockIdx.x;
    const int tid = threadIdx.x;
    const float* P = params + (size_t)b * NPARAMS;

    if (tid < DIM) s_eps[tid] = eps[(size_t)b * DIM + tid];

    // ---- Build Lt (transposed L) in shared memory ----
    // Packed layout: L_flat[p], p = i*128 + j:
    //   p < 8128  -> params[256 + p]
    //   p >= 8128 -> params[16511 - p]
    // diag: log value kept raw, L[i][i] = exp(raw)
    // off-diag: raw / sqrt(i+1)
    #pragma unroll 4
    for (int p = tid; p < DIM*DIM; p += NTHREADS) {
        int i = p >> 7;
        int j = p & 127;
        float v = 0.0f;
        if (j <= i) {
            float raw = (p < 8128) ? P[256 + p] : P[16511 - p];
            if (i == j) {
                s_ld[i] = raw;
                v = expf(raw);
            } else {
                v = raw * rsqrtf((float)(i + 1));
            }
        }
        Lt[j][i] = v;
    }
    __syncthreads();

    // ---- Sigma = L * L^T, lower 8x8 tiles only (136 tiles), mirrored ----
    // Tiles enumerated tx-major (ascending j-bound) so warps have uniform
    // loop trip counts: thread t < 136 -> (ty, tx) with tx <= ty.
    if (tid < 136) {
        int idx = tid;
        int tx = 0;
        while (idx >= 16 - tx) { idx -= 16 - tx; tx++; }
        int ty = tx + idx;

        const int i0 = ty * 8;
        const int k0 = tx * 8;
        const int jmax = (tx + 1) * 8;   // covers min(i,k)+1; zeros pad the rest

        float acc[8][8];
        #pragma unroll
        for (int r = 0; r < 8; r++)
            #pragma unroll
            for (int c = 0; c < 8; c++) acc[r][c] = 0.0f;

        for (int j = 0; j < jmax; j++) {
            float4 a0 = *(const float4*)&Lt[j][i0];
            float4 a1 = *(const float4*)&Lt[j][i0 + 4];
            float4 b0 = *(const float4*)&Lt[j][k0];
            float4 b1 = *(const float4*)&Lt[j][k0 + 4];
            float ai[8] = {a0.x, a0.y, a0.z, a0.w, a1.x, a1.y, a1.z, a1.w};
            float bk[8] = {b0.x, b0.y, b0.z, b0.w, b1.x, b1.y, b1.z, b1.w};
            #pragma unroll
            for (int r = 0; r < 8; r++)
                #pragma unroll
                for (int c = 0; c < 8; c++)
                    acc[r][c] = fmaf(ai[r], bk[c], acc[r][c]);
        }

        float* Sg = sigma + (size_t)b * DIM * DIM;

        // direct tile
        #pragma unroll
        for (int r = 0; r < 8; r++) {
            float4 v0 = make_float4(acc[r][0], acc[r][1], acc[r][2], acc[r][3]);
            float4 v1 = make_float4(acc[r][4], acc[r][5], acc[r][6], acc[r][7]);
            *(float4*)&Sg[(size_t)(i0 + r) * DIM + k0]     = v0;
            *(float4*)&Sg[(size_t)(i0 + r) * DIM + k0 + 4] = v1;
        }

        if (tx != ty) {
            // mirrored tile (transpose of acc)
            #pragma unroll
            for (int c = 0; c < 8; c++) {
                float4 w0 = make_float4(acc[0][c], acc[1][c], acc[2][c], acc[3][c]);
                float4 w1 = make_float4(acc[4][c], acc[5][c], acc[6][c], acc[7][c]);
                *(float4*)&Sg[(size_t)(k0 + c) * DIM + i0]     = w0;
                *(float4*)&Sg[(size_t)(k0 + c) * DIM + i0 + 4] = w1;
            }
        } else {
            #pragma unroll
            for (int r = 0; r < 8; r++) s_diag[i0 + r] = acc[r][r];
        }
    }
    __syncthreads();

    // ---- sample = mean + L*eps, and kl terms ----
    float t = 0.0f;
    if (tid < DIM) {
        float accs = 0.0f;
        for (int j = 0; j <= tid; j++)
            accs = fmaf(Lt[j][tid], s_eps[j], accs);
        float m = P[tid];
        sample[(size_t)b * DIM + tid] = m + accs;
        t = s_diag[tid] - 1.0f + m * m - 2.0f * s_ld[tid];
    }
    // reduce t over the 128 active lanes (lanes >=128 contribute 0)
    #pragma unroll
    for (int o = 16; o > 0; o >>= 1)
        t += __shfl_down_sync(0xffffffffu, t, o);
    if ((tid & 31) == 0 && tid < DIM) s_red[tid >> 5] = t;
    __syncthreads();
    if (tid == 0)
        kl[b] = 0.5f * (s_red[0] + s_red[1] + s_red[2] + s_red[3]);
}

extern "C" void kernel_launch(void* const* d_in, const int* in_sizes, int n_in,
                              void* d_out, int out_size)
{
    const float* params = (const float*)d_in[0];
    const float* eps    = (const float*)d_in[1];
    const int B = in_sizes[0] / NPARAMS;

    float* out    = (float*)d_out;
    float* sample = out;                       // B * 128
    float* kl     = out + (size_t)B * DIM;     // B
    float* sigma  = kl + B;                    // B * 128 * 128

    const size_t smem = SMEM_FLOATS * sizeof(float);
    cudaFuncSetAttribute(fld_kernel,
                         cudaFuncAttributeMaxDynamicSharedMemorySize,
                         (int)smem);
    fld_kernel<<<B, NTHREADS, smem>>>(params, eps, sample, kl, sigma);
}

// round 3
// speedup vs baseline: 1.8338x; 1.8338x over previous
#include <cuda_runtime.h>
#include <cstdint>
#include <math.h>

#define DIM      128
#define NPARAMS  8384
#define NT       512            // 16 warps

#define RS       136            // smem row stride in floats (128 + 8 pad)

// smem float offsets
#define OFF_L    0              // L (perm layout) / Sigma staging: 128*136
#define OFF_EPS  (128 * RS)     // eps, perm layout, 128
#define OFF_LD   (OFF_EPS + 128)  // log-diag, 128
#define OFF_RED  (OFF_LD + 128)   // 16
#define SMEM_FLOATS (OFF_RED + 16)

// Column permutation: within each 8-wide k-group, store k at position
// 2*(k%4) + (k/4)  ->  (k, k+4) are adjacent words (enables LDS.64 frags).
__device__ __forceinline__ int permcol(int j) {
    return (j & ~7) | (((j & 3) << 1) | ((j >> 2) & 1));
}

__global__ __launch_bounds__(NT, 2)
void fld_mma_kernel(const float* __restrict__ params,
                    const float* __restrict__ eps,
                    float* __restrict__ sample,
                    float* __restrict__ kl,
                    float* __restrict__ sigma)
{
    extern __shared__ float smf[];

    const int b   = blockIdx.x;
    const int tid = threadIdx.x;
    const int wid = tid >> 5;
    const int lid = tid & 31;
    const float* P = params + (size_t)b * NPARAMS;

    if (tid < DIM)
        smf[OFF_EPS + permcol(tid)] = eps[(size_t)b * DIM + tid];

    // ---- Build L (tf32-rounded) into perm-layout smem ----
    // Packed: L_flat[p], p=i*128+j: p<8128 -> params[256+p]; else params[16511-p]
    // diag: exp(raw) (raw kept in s_ld); off-diag: raw * rsqrt(i+1); upper: 0
    #pragma unroll
    for (int q = 0; q < (DIM * DIM) / NT; q++) {
        int p = tid + q * NT;
        int i = p >> 7;
        int j = p & 127;
        float v = 0.0f;
        if (j <= i) {
            float raw = (p < 8128) ? P[256 + p] : P[16511 - p];
            if (i == j) {
                smf[OFF_LD + i] = raw;
                v = expf(raw);
            } else {
                v = raw * rsqrtf((float)(i + 1));
            }
        }
        uint32_t tv;
        asm("cvt.rna.tf32.f32 %0, %1;" : "=r"(tv) : "f"(v));
        *(uint32_t*)&smf[OFF_L + i * RS + permcol(j)] = tv;
    }
    __syncthreads();

    // ---- Sigma = L * L^T via mma.sync m16n8k8 tf32 ----
    // Warp w: rows [16*(w&7), +16), cols [64*(w>>3), +64) -> 8 n-tiles.
    const int m0 = (wid & 7) * 16;
    const int nb = (wid >> 3) * 64;
    const int gr = lid >> 2;        // group id 0..7
    const int tg = lid & 3;         // thread in group 0..3

    float acc[8][4];
    #pragma unroll
    for (int t = 0; t < 8; t++)
        #pragma unroll
        for (int c = 0; c < 4; c++) acc[t][c] = 0.0f;

    const float* arow0 = smf + OFF_L + (size_t)(m0 + gr) * RS + 2 * tg;
    const float* arow1 = arow0 + 8 * RS;
    const float* brow  = smf + OFF_L + (size_t)(nb + gr) * RS + 2 * tg;

    #pragma unroll 4
    for (int ks = 0; ks < 16; ks++) {
        const int k0 = ks * 8;
        uint2 a02 = *(const uint2*)(arow0 + k0);   // (a0, a2)
        uint2 a13 = *(const uint2*)(arow1 + k0);   // (a1, a3)
        #pragma unroll
        for (int nt = 0; nt < 8; nt++) {
            uint2 b01 = *(const uint2*)(brow + (size_t)nt * 8 * RS + k0);
            asm volatile(
                "mma.sync.aligned.m16n8k8.row.col.f32.tf32.tf32.f32 "
                "{%0,%1,%2,%3}, {%4,%5,%6,%7}, {%8,%9}, {%0,%1,%2,%3};"
                : "+f"(acc[nt][0]), "+f"(acc[nt][1]),
                  "+f"(acc[nt][2]), "+f"(acc[nt][3])
                : "r"(a02.x), "r"(a13.x), "r"(a02.y), "r"(a13.y),
                  "r"(b01.x), "r"(b01.y));
        }
    }

    // ---- sample = mean + L*eps ; kl terms (tid < 128, reads L before overwrite)
    float t = 0.0f;
    if (tid < DIM) {
        float accs = 0.0f, sq = 0.0f;
        const float* Lr = smf + OFF_L + (size_t)tid * RS;
        const float* se = smf + OFF_EPS;
        #pragma unroll 8
        for (int q = 0; q < DIM; q += 4) {
            float4 lv = *(const float4*)(Lr + q);
            float4 ev = *(const float4*)(se + q);
            accs = fmaf(lv.x, ev.x, accs);
            accs = fmaf(lv.y, ev.y, accs);
            accs = fmaf(lv.z, ev.z, accs);
            accs = fmaf(lv.w, ev.w, accs);
            sq = fmaf(lv.x, lv.x, sq);
            sq = fmaf(lv.y, lv.y, sq);
            sq = fmaf(lv.z, lv.z, sq);
            sq = fmaf(lv.w, lv.w, sq);
        }
        float m = P[tid];
        sample[(size_t)b * DIM + tid] = m + accs;
        t = sq - 1.0f + m * m - 2.0f * smf[OFF_LD + tid];
    }
    #pragma unroll
    for (int o = 16; o > 0; o >>= 1)
        t += __shfl_down_sync(0xffffffffu, t, o);
    if (lid == 0 && tid < DIM) smf[OFF_RED + wid] = t;

    __syncthreads();   // L reads done everywhere; s_red ready

    if (tid == 0)
        kl[b] = 0.5f * (smf[OFF_RED] + smf[OFF_RED + 1] +
                        smf[OFF_RED + 2] + smf[OFF_RED + 3]);

    // ---- Stage D-frags into smem (overwrites L buffer), conflict-free ----
    {
        float* s0 = smf + OFF_L + (size_t)(m0 + gr) * RS + nb + 2 * tg;
        float* s1 = s0 + 8 * RS;
        #pragma unroll
        for (int nt = 0; nt < 8; nt++) {
            *(float2*)(s0 + nt * 8) = make_float2(acc[nt][0], acc[nt][1]);
            *(float2*)(s1 + nt * 8) = make_float2(acc[nt][2], acc[nt][3]);
        }
    }
    __syncthreads();

    // ---- Coalesced copy-out: staging -> Sigma ----
    {
        float* Sg = sigma + (size_t)b * DIM * DIM;
        #pragma unroll
        for (int q = 0; q < (DIM * DIM / 4) / NT; q++) {
            int tq  = tid + q * NT;
            int row = tq >> 5;
            int c4  = (tq & 31) << 2;
            float4 v = *(const float4*)(smf + OFF_L + (size_t)row * RS + c4);
            *(float4*)(Sg + (size_t)row * DIM + c4) = v;
        }
    }
}

extern "C" void kernel_launch(void* const* d_in, const int* in_sizes, int n_in,
                              void* d_out, int out_size)
{
    const float* params = (const float*)d_in[0];
    const float* eps    = (const float*)d_in[1];
    const int B = in_sizes[0] / NPARAMS;

    float* out    = (float*)d_out;
    float* sample = out;                       // B * 128
    float* kl     = out + (size_t)B * DIM;     // B
    float* sigma  = kl + B;                    // B * 128 * 128

    const int smem = SMEM_FLOATS * sizeof(float);
    cudaFuncSetAttribute(fld_mma_kernel,
                         cudaFuncAttributeMaxDynamicSharedMemorySize, smem);
    fld_mma_kernel<<<B, NT, smem>>>(params, eps, sample, kl, sigma);
}